// round 2
// baseline (speedup 1.0000x reference)
#include <cuda_runtime.h>
#include <math.h>
#include <stdint.h>

// ---------------------------------------------------------------------------
// GRAN model forward, fp32. Zero runtime-API calls in kernel_launch except
// kernel launches (all scratch is __device__ globals referenced by name).
// B=1024 S=7 E=256 H=4 DH=64 L=12 INNER=512 VOC=50000 NREL=200
// ---------------------------------------------------------------------------

#define BQ     1024
#define SQ     7
#define EQ     256
#define HQ     4
#define DHQ    64
#define LQ     12
#define INNERQ 512
#define VOCQ   50000
#define MROWS  (BQ*SQ)   // 7168

// -------------------- static device scratch (allocation-free) ---------------
__device__ float g_x  [MROWS*EQ];
__device__ float g_q  [MROWS*EQ];
__device__ float g_k  [MROWS*EQ];
__device__ float g_v  [MROWS*EQ];
__device__ float g_ctx[MROWS*EQ];
__device__ float g_o  [MROWS*EQ];
__device__ float g_h  [MROWS*INNERQ];
__device__ float g_ek [SQ*SQ*DHQ];
__device__ float g_ev [SQ*SQ*DHQ];
__device__ float g_hm [BQ*EQ];
__device__ float g_losses[BQ];
__device__ float g_fc [(size_t)BQ*VOCQ];   // fallback fc buffer

// -------------------- helpers ----------------------------------------------
__device__ __forceinline__ float gelu_f(float x) {
    return 0.5f * x * (1.0f + erff(x * 0.70710678118654752440f));
}

__device__ __forceinline__ float blk_sum256(float v, float* sh) {
    #pragma unroll
    for (int o = 16; o > 0; o >>= 1) v += __shfl_xor_sync(0xffffffffu, v, o);
    if ((threadIdx.x & 31) == 0) sh[threadIdx.x >> 5] = v;
    __syncthreads();
    float s = sh[0] + sh[1] + sh[2] + sh[3] + sh[4] + sh[5] + sh[6] + sh[7];
    __syncthreads();
    return s;
}

// type-indicator: ti(col, mask_type)
__device__ __forceinline__ float ti_of(int c, float mt) {
    return (c < 2) ? 0.0f
         : ((c < 202) ? (mt < 0.0f ? 1.0f : 0.0f)
                      : (mt > 0.0f ? 1.0f : 0.0f));
}

// -------------------- edge bias precompute ----------------------------------
__global__ void edge_kernel(const int* __restrict__ el,
                            const float* __restrict__ ekw,
                            const float* __restrict__ evw)
{
    int i = blockIdx.x * blockDim.x + threadIdx.x;
    if (i >= SQ * SQ * DHQ) return;
    int ij = i / DHQ, d = i % DHQ;
    int lab = el[ij];
    float s = (lab > 0) ? 1.0f : 0.0f;
    g_ek[i] = ekw[lab * DHQ + d] * s;
    g_ev[i] = evw[lab * DHQ + d] * s;
}

// -------------------- LayerNorm family --------------------------------------
__global__ void __launch_bounds__(256)
ln_embed_kernel(const float* __restrict__ emb, const int* __restrict__ ids,
                const float* __restrict__ g, const float* __restrict__ b)
{
    __shared__ float sh[8];
    int row = blockIdx.x, t = threadIdx.x;
    float v = emb[(size_t)ids[row] * EQ + t];
    float mu = blk_sum256(v, sh) * (1.0f / EQ);
    float d = v - mu;
    float var = blk_sum256(d * d, sh) * (1.0f / EQ);
    g_x[(size_t)row * EQ + t] = d * rsqrtf(var + 1e-12f) * g[t] + b[t];
}

// g_x = LN(g_x + g_o)
__global__ void __launch_bounds__(256)
ln_res_kernel(const float* __restrict__ g, const float* __restrict__ b)
{
    __shared__ float sh[8];
    int row = blockIdx.x, t = threadIdx.x;
    size_t o = (size_t)row * EQ + t;
    float v = g_x[o] + g_o[o];
    float mu = blk_sum256(v, sh) * (1.0f / EQ);
    float d = v - mu;
    float var = blk_sum256(d * d, sh) * (1.0f / EQ);
    g_x[o] = d * rsqrtf(var + 1e-12f) * g[t] + b[t];
}

// g_hm[b] = LN(gelu(g_x[b, mask_pos[b]]))
__global__ void __launch_bounds__(256)
ln_head_kernel(const int* __restrict__ pos,
               const float* __restrict__ g, const float* __restrict__ b)
{
    __shared__ float sh[8];
    int row = blockIdx.x, t = threadIdx.x;
    float v = gelu_f(g_x[((size_t)row * SQ + pos[row]) * EQ + t]);
    float mu = blk_sum256(v, sh) * (1.0f / EQ);
    float d = v - mu;
    float var = blk_sum256(d * d, sh) * (1.0f / EQ);
    g_hm[(size_t)row * EQ + t] = d * rsqrtf(var + 1e-7f) * g[t] + b[t];
}

// -------------------- SGEMM core 64x64x16, 256 thr, 4x4/thr -----------------
// C[M,N] = A[M,K] @ B + bias. BT=false: B[K,N]. BT=true: B[N,K] (NT GEMM).
// EPI: 0 bias, 1 bias+gelu, 2 fc (bias + 1e6*(ti-1)).
template<bool BT, int EPI>
__device__ __forceinline__
void gemm_core(const float* __restrict__ A, const float* __restrict__ Bw,
               const float* __restrict__ bias, float* __restrict__ C,
               int M, int N, int K, const float* __restrict__ mtype)
{
    __shared__ float As[16][68];
    __shared__ float Bs[16][68];
    int tid = threadIdx.x;
    int tx = tid & 15, ty = tid >> 4;
    int bm = blockIdx.y * 64, bn = blockIdx.x * 64;

    float acc[4][4] = {};
    int ar = tid >> 2, akq = tid & 3;

    for (int k0 = 0; k0 < K; k0 += 16) {
        float4 a4 = *reinterpret_cast<const float4*>(
            A + (size_t)(bm + ar) * K + k0 + akq * 4);
        As[akq * 4 + 0][ar] = a4.x; As[akq * 4 + 1][ar] = a4.y;
        As[akq * 4 + 2][ar] = a4.z; As[akq * 4 + 3][ar] = a4.w;

        if (!BT) {
            int kr = tid >> 4, nq = tid & 15;
            float4 b4 = *reinterpret_cast<const float4*>(
                Bw + (size_t)(k0 + kr) * N + bn + nq * 4);
            *reinterpret_cast<float4*>(&Bs[kr][nq * 4]) = b4;
        } else {
            int nr = tid >> 2, kq = tid & 3;
            float4 b4 = make_float4(0.f, 0.f, 0.f, 0.f);
            if (bn + nr < N)
                b4 = *reinterpret_cast<const float4*>(
                    Bw + (size_t)(bn + nr) * K + k0 + kq * 4);
            Bs[kq * 4 + 0][nr] = b4.x; Bs[kq * 4 + 1][nr] = b4.y;
            Bs[kq * 4 + 2][nr] = b4.z; Bs[kq * 4 + 3][nr] = b4.w;
        }
        __syncthreads();

        #pragma unroll
        for (int kk = 0; kk < 16; kk++) {
            float4 av = *reinterpret_cast<const float4*>(&As[kk][ty * 4]);
            float4 bv = *reinterpret_cast<const float4*>(&Bs[kk][tx * 4]);
            float aa[4] = {av.x, av.y, av.z, av.w};
            float bb[4] = {bv.x, bv.y, bv.z, bv.w};
            #pragma unroll
            for (int i = 0; i < 4; i++)
                #pragma unroll
                for (int j = 0; j < 4; j++)
                    acc[i][j] += aa[i] * bb[j];
        }
        __syncthreads();
    }

    #pragma unroll
    for (int i = 0; i < 4; i++) {
        int r = bm + ty * 4 + i;
        float mt = 0.0f;
        if (EPI == 2) mt = mtype[r];
        #pragma unroll
        for (int j = 0; j < 4; j++) {
            int c = bn + tx * 4 + j;
            if (BT && c >= N) continue;
            float val = acc[i][j] + bias[c];
            if (EPI == 1) val = gelu_f(val);
            if (EPI == 2) val += 1e6f * (ti_of(c, mt) - 1.0f);
            C[(size_t)r * N + c] = val;
        }
    }
}

// ---- wrappers with fixed global wiring --------------------------------------
// QKV fused: blockIdx.z selects {q,k,v}
__global__ void __launch_bounds__(256)
k_qkv(const float* __restrict__ Wq, const float* __restrict__ Wk,
      const float* __restrict__ Wv, const float* __restrict__ bq,
      const float* __restrict__ bk, const float* __restrict__ bv)
{
    int z = blockIdx.z;
    const float* W = (z == 0) ? Wq : (z == 1) ? Wk : Wv;
    const float* b = (z == 0) ? bq : (z == 1) ? bk : bv;
    float* C = (z == 0) ? g_q : (z == 1) ? g_k : g_v;
    gemm_core<false, 0>(g_x, W, b, C, MROWS, EQ, EQ, nullptr);
}

__global__ void __launch_bounds__(256)
k_oproj(const float* __restrict__ W, const float* __restrict__ b)
{ gemm_core<false, 0>(g_ctx, W, b, g_o, MROWS, EQ, EQ, nullptr); }

__global__ void __launch_bounds__(256)
k_ffn1(const float* __restrict__ W, const float* __restrict__ b)
{ gemm_core<false, 1>(g_x, W, b, g_h, MROWS, INNERQ, EQ, nullptr); }

__global__ void __launch_bounds__(256)
k_ffn2(const float* __restrict__ W, const float* __restrict__ b)
{ gemm_core<false, 0>(g_h, W, b, g_o, MROWS, EQ, INNERQ, nullptr); }

// fc: A = g_hm [B,E], B = node_emb [VOC,E] (NT), out selectable
__global__ void __launch_bounds__(256)
k_fc(const float* __restrict__ emb, const float* __restrict__ bias,
     const float* __restrict__ mtype, float* outp, int use_out)
{
    float* C = use_out ? outp : g_fc;
    gemm_core<true, 2>(g_hm, emb, bias, C, BQ, VOCQ, EQ, mtype);
}

// -------------------- relational attention (S=7) -----------------------------
__global__ void __launch_bounds__(256)
attn_kernel(const float* __restrict__ mask)
{
    __shared__ float sq[SQ][EQ], sk[SQ][EQ], sv[SQ][EQ];
    __shared__ float sek[SQ * SQ][DHQ], sev[SQ * SQ][DHQ];
    __shared__ float sc[HQ][SQ][8];
    __shared__ float sm[SQ];

    int b = blockIdx.x, t = threadIdx.x;
    size_t base = (size_t)b * SQ * EQ;

    for (int i = t; i < SQ * EQ; i += 256) {
        sq[0][i] = g_q[base + i];
        sk[0][i] = g_k[base + i];
        sv[0][i] = g_v[base + i];
    }
    for (int i = t; i < SQ * SQ * DHQ; i += 256) {
        sek[0][i] = g_ek[i];
        sev[0][i] = g_ev[i];
    }
    if (t < SQ) sm[t] = mask[b * SQ + t];
    __syncthreads();

    const float scale = 0.125f;  // 1/sqrt(64)
    if (t < HQ * SQ * SQ) {
        int h = t / 49, r = t % 49, i = r / 7, j = r % 7;
        const float* qp = &sq[i][h * DHQ];
        const float* kp = &sk[j][h * DHQ];
        const float* ep = &sek[i * SQ + j][0];
        float s = 0.0f;
        #pragma unroll
        for (int d = 0; d < DHQ; d++) s += qp[d] * (kp[d] + ep[d]);
        sc[h][i][j] = s * scale + 1e6f * (sm[i] * sm[j] - 1.0f);
    }
    __syncthreads();

    if (t < HQ * SQ) {
        int h = t / 7, i = t % 7;
        float mx = sc[h][i][0];
        #pragma unroll
        for (int j = 1; j < 7; j++) mx = fmaxf(mx, sc[h][i][j]);
        float e[7], sum = 0.0f;
        #pragma unroll
        for (int j = 0; j < 7; j++) { e[j] = expf(sc[h][i][j] - mx); sum += e[j]; }
        float inv = 1.0f / sum;
        #pragma unroll
        for (int j = 0; j < 7; j++) sc[h][i][j] = e[j] * inv;
    }
    __syncthreads();

    int h = t >> 6, d = t & 63;
    #pragma unroll
    for (int i = 0; i < SQ; i++) {
        float a = 0.0f;
        #pragma unroll
        for (int j = 0; j < 7; j++)
            a += sc[h][i][j] * (sv[j][t] + sev[i * SQ + j][d]);
        g_ctx[base + (size_t)i * EQ + t] = a;
    }
}

// -------------------- per-row loss -------------------------------------------
__global__ void __launch_bounds__(256)
row_loss_kernel(const float* outp, int use_out,
                const float* __restrict__ mtype, const int* __restrict__ label)
{
    __shared__ float sh[8];
    int b = blockIdx.x, t = threadIdx.x;
    const float* row = (use_out ? outp : (const float*)g_fc) + (size_t)b * VOCQ;

    float mx = -3.4e38f;
    for (int vv = t; vv < VOCQ; vv += 256) mx = fmaxf(mx, row[vv]);
    #pragma unroll
    for (int o = 16; o > 0; o >>= 1) mx = fmaxf(mx, __shfl_xor_sync(0xffffffffu, mx, o));
    if ((t & 31) == 0) sh[t >> 5] = mx;
    __syncthreads();
    mx = fmaxf(fmaxf(fmaxf(sh[0], sh[1]), fmaxf(sh[2], sh[3])),
               fmaxf(fmaxf(sh[4], sh[5]), fmaxf(sh[6], sh[7])));
    __syncthreads();

    float mt = mtype[b];
    float se = 0.0f, cs = 0.0f;
    for (int vv = t; vv < VOCQ; vv += 256) {
        float f = row[vv];
        se += expf(f - mx);
        cs += ti_of(vv, mt) * f;
    }
    se = blk_sum256(se, sh);
    cs = blk_sum256(cs, sh);

    if (t == 0) {
        float Z = mx + logf(se);
        float C = (mt < 0.0f) ? 200.0f : (float)(VOCQ - 202);
        int lab = label[b];
        float Nc = C - ti_of(lab, mt);
        float lpl = row[lab] - Z;
        float Sti = cs - C * Z;   // sum over candidates of logprob
        g_losses[b] = -(0.9f * lpl + 0.1f * (Sti - lpl) / Nc);
    }
}

__global__ void __launch_bounds__(256)
loss_reduce_kernel(float* __restrict__ out)
{
    __shared__ float sh[8];
    float s = 0.0f;
    for (int i = threadIdx.x; i < BQ; i += 256) s += g_losses[i];
    s = blk_sum256(s, sh);
    if (threadIdx.x == 0) out[0] = s / (float)BQ;
}

// -------------------- launch ------------------------------------------------
extern "C" void kernel_launch(void* const* d_in, const int* in_sizes, int n_in,
                              void* d_out, int out_size)
{
    (void)in_sizes; (void)n_in;
    const int*   input_ids   = (const int*)  d_in[0];
    const float* input_mask  = (const float*)d_in[1];
    const int*   edge_labels = (const int*)  d_in[2];
    const int*   mask_pos    = (const int*)  d_in[3];
    const int*   mask_label  = (const int*)  d_in[4];
    const float* mask_type   = (const float*)d_in[5];
    const float* node_emb    = (const float*)d_in[6];
    const float* ln1_g = (const float*)d_in[7];
    const float* ln1_b = (const float*)d_in[8];
    const float* ek_w  = (const float*)d_in[9];
    const float* ev_w  = (const float*)d_in[10];
    const float* Wq = (const float*)d_in[11]; const float* bq = (const float*)d_in[12];
    const float* Wk = (const float*)d_in[13]; const float* bk = (const float*)d_in[14];
    const float* Wv = (const float*)d_in[15]; const float* bv = (const float*)d_in[16];
    const float* Wo = (const float*)d_in[17]; const float* bo = (const float*)d_in[18];
    const float* lna_g = (const float*)d_in[19]; const float* lna_b = (const float*)d_in[20];
    const float* W1 = (const float*)d_in[21]; const float* b1 = (const float*)d_in[22];
    const float* W2 = (const float*)d_in[23]; const float* b2 = (const float*)d_in[24];
    const float* lnf_g = (const float*)d_in[25]; const float* lnf_b = (const float*)d_in[26];
    const float* ln2_g = (const float*)d_in[27]; const float* ln2_b = (const float*)d_in[28];
    const float* fc2_b = (const float*)d_in[29];

    float* out = (float*)d_out;
    const long long FCN = (long long)BQ * VOCQ;
    float* fc_ptr = nullptr;     // where fc_out goes if inside d_out
    float* loss_ptr = nullptr;
    int fc_in_out = 0;
    if ((long long)out_size >= FCN + 1) {      // [loss, fc_out] flattened
        loss_ptr = out;
        fc_ptr = out + (long long)out_size - FCN;
        fc_in_out = 1;
    } else if ((long long)out_size == FCN) {   // fc_out only
        fc_ptr = out;
        fc_in_out = 1;
    } else {                                   // loss only
        loss_ptr = out;
    }

    edge_kernel<<<(SQ * SQ * DHQ + 255) / 256, 256>>>(edge_labels, ek_w, ev_w);
    ln_embed_kernel<<<MROWS, 256>>>(node_emb, input_ids, ln1_g, ln1_b);

    dim3 gqkv(EQ / 64, MROWS / 64, 3);
    dim3 g256(EQ / 64, MROWS / 64);
    dim3 g512(INNERQ / 64, MROWS / 64);

    for (int l = 0; l < LQ; l++) {
        size_t we = (size_t)l * EQ * EQ;
        k_qkv<<<gqkv, 256>>>(Wq + we, Wk + we, Wv + we,
                             bq + l * EQ, bk + l * EQ, bv + l * EQ);
        attn_kernel<<<BQ, 256>>>(input_mask);
        k_oproj<<<g256, 256>>>(Wo + we, bo + l * EQ);
        ln_res_kernel<<<MROWS, 256>>>(lna_g + l * EQ, lna_b + l * EQ);
        k_ffn1<<<g512, 256>>>(W1 + (size_t)l * EQ * INNERQ, b1 + l * INNERQ);
        k_ffn2<<<g256, 256>>>(W2 + (size_t)l * INNERQ * EQ, b2 + l * EQ);
        ln_res_kernel<<<MROWS, 256>>>(lnf_g + l * EQ, lnf_b + l * EQ);
    }

    ln_head_kernel<<<BQ, 256>>>(mask_pos, ln2_g, ln2_b);

    dim3 gfc((VOCQ + 63) / 64, BQ / 64);
    k_fc<<<gfc, 256>>>(node_emb, fc2_b, mask_type, fc_ptr, fc_in_out);

    row_loss_kernel<<<BQ, 256>>>(fc_ptr, fc_in_out, mask_type, mask_label);
    if (loss_ptr) loss_reduce_kernel<<<1, 256>>>(loss_ptr);
}

// round 6
// speedup vs baseline: 1.2246x; 1.2246x over previous
#include <cuda_runtime.h>
#include <math.h>
#include <stdint.h>

// ---------------------------------------------------------------------------
// GRAN model forward, fp32, round 6: identical to round 5 (which never ran —
// container-level infra failure; round 4 proved real kernel faults get
// reported cleanly). Misaligned-store fix for fc output retained.
// B=1024 S=7 E=256 H=4 DH=64 L=12 INNER=512 VOC=50000
// ---------------------------------------------------------------------------

#define BQ     1024
#define SQ     7
#define EQ     256
#define HQ     4
#define DHQ    64
#define LQ     12
#define INNERQ 512
#define VOCQ   50000
#define MROWS  (BQ*SQ)   // 7168

// -------------------- static device scratch ---------------------------------
__device__ float g_x  [MROWS*EQ];
__device__ float g_q  [MROWS*EQ];
__device__ float g_k  [MROWS*EQ];
__device__ float g_v  [MROWS*EQ];
__device__ float g_ctx[MROWS*EQ];
__device__ float g_h  [MROWS*INNERQ];
__device__ float g_ek [SQ*SQ*DHQ];
__device__ float g_ev [SQ*SQ*DHQ];
__device__ float g_hm [BQ*EQ];
__device__ float g_losses[BQ];
__device__ float g_fc [(size_t)BQ*VOCQ];   // fallback fc buffer

// -------------------- helpers -----------------------------------------------
__device__ __forceinline__ float gelu_f(float x) {
    return 0.5f * x * (1.0f + erff(x * 0.70710678118654752440f));
}

__device__ __forceinline__ float warp_sum(float v) {
    #pragma unroll
    for (int o = 16; o > 0; o >>= 1) v += __shfl_xor_sync(0xffffffffu, v, o);
    return v;
}

__device__ __forceinline__ float blk_sum256(float v, float* sh) {
    v = warp_sum(v);
    if ((threadIdx.x & 31) == 0) sh[threadIdx.x >> 5] = v;
    __syncthreads();
    float s = sh[0] + sh[1] + sh[2] + sh[3] + sh[4] + sh[5] + sh[6] + sh[7];
    __syncthreads();
    return s;
}

__device__ __forceinline__ float ti_of(int c, float mt) {
    return (c < 2) ? 0.0f
         : ((c < 202) ? (mt < 0.0f ? 1.0f : 0.0f)
                      : (mt > 0.0f ? 1.0f : 0.0f));
}

// -------------------- edge bias precompute -----------------------------------
__global__ void edge_kernel(const int* __restrict__ el,
                            const float* __restrict__ ekw,
                            const float* __restrict__ evw)
{
    int i = blockIdx.x * blockDim.x + threadIdx.x;
    if (i >= SQ * SQ * DHQ) return;
    int ij = i / DHQ, d = i % DHQ;
    int lab = el[ij];
    float s = (lab > 0) ? 1.0f : 0.0f;
    g_ek[i] = ekw[lab * DHQ + d] * s;
    g_ev[i] = evw[lab * DHQ + d] * s;
}

// -------------------- standalone LayerNorms ----------------------------------
__global__ void __launch_bounds__(256)
ln_embed_kernel(const float* __restrict__ emb, const int* __restrict__ ids,
                const float* __restrict__ g, const float* __restrict__ b)
{
    __shared__ float sh[8];
    int row = blockIdx.x, t = threadIdx.x;
    float v = emb[(size_t)ids[row] * EQ + t];
    float mu = blk_sum256(v, sh) * (1.0f / EQ);
    float d = v - mu;
    float var = blk_sum256(d * d, sh) * (1.0f / EQ);
    g_x[(size_t)row * EQ + t] = d * rsqrtf(var + 1e-12f) * g[t] + b[t];
}

__global__ void __launch_bounds__(256)
ln_head_kernel(const int* __restrict__ pos,
               const float* __restrict__ g, const float* __restrict__ b)
{
    __shared__ float sh[8];
    int row = blockIdx.x, t = threadIdx.x;
    float v = gelu_f(g_x[((size_t)row * SQ + pos[row]) * EQ + t]);
    float mu = blk_sum256(v, sh) * (1.0f / EQ);
    float d = v - mu;
    float var = blk_sum256(d * d, sh) * (1.0f / EQ);
    g_hm[(size_t)row * EQ + t] = d * rsqrtf(var + 1e-7f) * g[t] + b[t];
}

// -------------------- SGEMM 128x64, double-buffered --------------------------
// C[M,N] = A[M,K] @ B + bias. BT=false: B[K,N]. BT=true: B[N,K].
// EPI: 0 bias, 1 bias+gelu, 2 fc (bias + 1e6*(ti-1)).
template<bool BT, int EPI>
__device__ __forceinline__
void gemm128x64_core(const float* __restrict__ A, const float* __restrict__ Bw,
                     const float* __restrict__ bias, float* __restrict__ C,
                     int M, int N, int K, const float* __restrict__ mtype)
{
    __shared__ __align__(16) float As[2][16][132];
    __shared__ __align__(16) float Bs[2][16][68];
    const int tid = threadIdx.x;
    const int bm = blockIdx.y * 128, bn = blockIdx.x * 64;
    const int tx = tid & 15, ty = tid >> 4;
    const int arow = tid >> 2, akq = tid & 3;      // A loads: 2 rows per thread
    const int bkr = tid >> 4, bnq = tid & 15;      // B (KN) load
    const int bnr = tid >> 2, bkq = tid & 3;       // B (NK) load

    float acc[8][4] = {};
    float4 pa0, pa1, pb;

    // ---- stage 0 direct ----
    pa0 = *reinterpret_cast<const float4*>(A + (size_t)(bm + arow) * K + akq * 4);
    pa1 = *reinterpret_cast<const float4*>(A + (size_t)(bm + arow + 64) * K + akq * 4);
    if (!BT) {
        pb = *reinterpret_cast<const float4*>(Bw + (size_t)bkr * N + bn + bnq * 4);
    } else {
        pb = make_float4(0.f, 0.f, 0.f, 0.f);
        if (bn + bnr < N)
            pb = *reinterpret_cast<const float4*>(Bw + (size_t)(bn + bnr) * K + bkq * 4);
    }
    {
        As[0][akq*4+0][arow] = pa0.x; As[0][akq*4+1][arow] = pa0.y;
        As[0][akq*4+2][arow] = pa0.z; As[0][akq*4+3][arow] = pa0.w;
        As[0][akq*4+0][arow+64] = pa1.x; As[0][akq*4+1][arow+64] = pa1.y;
        As[0][akq*4+2][arow+64] = pa1.z; As[0][akq*4+3][arow+64] = pa1.w;
        if (!BT) {
            *reinterpret_cast<float4*>(&Bs[0][bkr][bnq*4]) = pb;
        } else {
            Bs[0][bkq*4+0][bnr] = pb.x; Bs[0][bkq*4+1][bnr] = pb.y;
            Bs[0][bkq*4+2][bnr] = pb.z; Bs[0][bkq*4+3][bnr] = pb.w;
        }
    }
    __syncthreads();

    const int nk = K >> 4;
    int buf = 0;
    for (int s = 0; s < nk; s++) {
        const bool more = (s + 1 < nk);
        if (more) {
            int k0 = (s + 1) << 4;
            pa0 = *reinterpret_cast<const float4*>(A + (size_t)(bm + arow) * K + k0 + akq * 4);
            pa1 = *reinterpret_cast<const float4*>(A + (size_t)(bm + arow + 64) * K + k0 + akq * 4);
            if (!BT) {
                pb = *reinterpret_cast<const float4*>(Bw + (size_t)(k0 + bkr) * N + bn + bnq * 4);
            } else {
                pb = make_float4(0.f, 0.f, 0.f, 0.f);
                if (bn + bnr < N)
                    pb = *reinterpret_cast<const float4*>(Bw + (size_t)(bn + bnr) * K + k0 + bkq * 4);
            }
        }
        #pragma unroll
        for (int kk = 0; kk < 16; kk++) {
            float4 a0 = *reinterpret_cast<const float4*>(&As[buf][kk][ty*8]);
            float4 a1 = *reinterpret_cast<const float4*>(&As[buf][kk][ty*8+4]);
            float4 b0 = *reinterpret_cast<const float4*>(&Bs[buf][kk][tx*4]);
            float av[8] = {a0.x,a0.y,a0.z,a0.w,a1.x,a1.y,a1.z,a1.w};
            float bv[4] = {b0.x,b0.y,b0.z,b0.w};
            #pragma unroll
            for (int i = 0; i < 8; i++)
                #pragma unroll
                for (int j = 0; j < 4; j++)
                    acc[i][j] += av[i] * bv[j];
        }
        if (more) {
            int nb = buf ^ 1;
            As[nb][akq*4+0][arow] = pa0.x; As[nb][akq*4+1][arow] = pa0.y;
            As[nb][akq*4+2][arow] = pa0.z; As[nb][akq*4+3][arow] = pa0.w;
            As[nb][akq*4+0][arow+64] = pa1.x; As[nb][akq*4+1][arow+64] = pa1.y;
            As[nb][akq*4+2][arow+64] = pa1.z; As[nb][akq*4+3][arow+64] = pa1.w;
            if (!BT) {
                *reinterpret_cast<float4*>(&Bs[nb][bkr][bnq*4]) = pb;
            } else {
                Bs[nb][bkq*4+0][bnr] = pb.x; Bs[nb][bkq*4+1][bnr] = pb.y;
                Bs[nb][bkq*4+2][bnr] = pb.z; Bs[nb][bkq*4+3][bnr] = pb.w;
            }
            __syncthreads();
            buf = nb;
        }
    }

    // ---- epilogue ----
    // C may be 4-byte misaligned (harness d_out + 1); vectorize only if 16B-aligned.
    const bool cvec = ((reinterpret_cast<uintptr_t>(C) & 15) == 0);
    #pragma unroll
    for (int i = 0; i < 8; i++) {
        int r = bm + ty * 8 + i;
        float mt = 0.0f;
        if (EPI == 2) mt = mtype[r];
        int cb = bn + tx * 4;
        float vals[4];
        #pragma unroll
        for (int j = 0; j < 4; j++) {
            int c = cb + j;
            float val = acc[i][j] + bias[(c < N) ? c : 0];
            if (EPI == 1) val = gelu_f(val);
            if (EPI == 2) val += 1e6f * (ti_of(c, mt) - 1.0f);
            vals[j] = val;
        }
        if (cvec && (!BT || cb + 3 < N)) {
            float4 v4 = make_float4(vals[0], vals[1], vals[2], vals[3]);
            *reinterpret_cast<float4*>(C + (size_t)r * N + cb) = v4;
        } else {
            #pragma unroll
            for (int j = 0; j < 4; j++) {
                int c = cb + j;
                if (BT && c >= N) continue;
                C[(size_t)r * N + c] = vals[j];
            }
        }
    }
}

// ---- wrappers (ALL device-global wiring resolved inside kernels) ------------
__global__ void __launch_bounds__(256)
k_qkv(const float* __restrict__ Wq, const float* __restrict__ Wk,
      const float* __restrict__ Wv, const float* __restrict__ bq,
      const float* __restrict__ bk, const float* __restrict__ bv)
{
    int z = blockIdx.z;
    const float* W = (z == 0) ? Wq : (z == 1) ? Wk : Wv;
    const float* b = (z == 0) ? bq : (z == 1) ? bk : bv;
    float* C = (z == 0) ? g_q : (z == 1) ? g_k : g_v;
    gemm128x64_core<false, 0>(g_x, W, b, C, MROWS, EQ, EQ, nullptr);
}

__global__ void __launch_bounds__(256)
k_ffn1(const float* __restrict__ W, const float* __restrict__ b)
{ gemm128x64_core<false, 1>(g_x, W, b, g_h, MROWS, INNERQ, EQ, nullptr); }

__global__ void __launch_bounds__(256)
k_fc(const float* __restrict__ emb, const float* __restrict__ bias,
     const float* __restrict__ mtype, float* outp, int use_out)
{
    float* C = use_out ? outp : g_fc;
    gemm128x64_core<true, 2>(g_hm, emb, bias, C, BQ, VOCQ, EQ, mtype);
}

// -------------------- 32x256 GEMM with fused residual + LayerNorm ------------
// g_x = LN(g_x + src@W + bias); src selected INSIDE the kernel (src_sel:
// 0 -> g_ctx with K=256, 1 -> g_h with K=512). Warp = 4 full rows.
__global__ void __launch_bounds__(256)
k_projln(int src_sel, const float* __restrict__ W,
         const float* __restrict__ bias,
         const float* __restrict__ g, const float* __restrict__ b)
{
    const float* A = (src_sel == 0) ? g_ctx : g_h;
    const int K = (src_sel == 0) ? EQ : INNERQ;

    __shared__ __align__(16) float As[2][16][36];
    __shared__ __align__(16) float Bs[2][16][260];
    const int tid = threadIdx.x;
    const int bm = blockIdx.x * 32;
    const int tx = tid & 31, ty = tid >> 5;    // ty = warp id, owns rows ty*4..+3

    float acc[4][8] = {};
    float4 pa; float4 pbv[4];
    const int arow = tid >> 2, akq = tid & 3;  // valid when tid<128

    // stage 0
    if (tid < 128)
        pa = *reinterpret_cast<const float4*>(A + (size_t)(bm + arow) * K + akq * 4);
    #pragma unroll
    for (int u = 0; u < 4; u++) {
        int idx = tid + 256 * u, kr = idx >> 6, nq = idx & 63;
        pbv[u] = *reinterpret_cast<const float4*>(W + (size_t)kr * EQ + nq * 4);
    }
    if (tid < 128) {
        As[0][akq*4+0][arow] = pa.x; As[0][akq*4+1][arow] = pa.y;
        As[0][akq*4+2][arow] = pa.z; As[0][akq*4+3][arow] = pa.w;
    }
    #pragma unroll
    for (int u = 0; u < 4; u++) {
        int idx = tid + 256 * u, kr = idx >> 6, nq = idx & 63;
        *reinterpret_cast<float4*>(&Bs[0][kr][nq*4]) = pbv[u];
    }
    __syncthreads();

    const int nk = K >> 4;
    int buf = 0;
    for (int s = 0; s < nk; s++) {
        const bool more = (s + 1 < nk);
        if (more) {
            int k0 = (s + 1) << 4;
            if (tid < 128)
                pa = *reinterpret_cast<const float4*>(A + (size_t)(bm + arow) * K + k0 + akq * 4);
            #pragma unroll
            for (int u = 0; u < 4; u++) {
                int idx = tid + 256 * u, kr = idx >> 6, nq = idx & 63;
                pbv[u] = *reinterpret_cast<const float4*>(W + (size_t)(k0 + kr) * EQ + nq * 4);
            }
        }
        #pragma unroll
        for (int kk = 0; kk < 16; kk++) {
            float4 a4 = *reinterpret_cast<const float4*>(&As[buf][kk][ty*4]);
            float4 b0 = *reinterpret_cast<const float4*>(&Bs[buf][kk][tx*4]);
            float4 b1 = *reinterpret_cast<const float4*>(&Bs[buf][kk][128 + tx*4]);
            float av[4] = {a4.x,a4.y,a4.z,a4.w};
            float bv[8] = {b0.x,b0.y,b0.z,b0.w,b1.x,b1.y,b1.z,b1.w};
            #pragma unroll
            for (int i = 0; i < 4; i++)
                #pragma unroll
                for (int j = 0; j < 8; j++)
                    acc[i][j] += av[i] * bv[j];
        }
        if (more) {
            int nb = buf ^ 1;
            if (tid < 128) {
                As[nb][akq*4+0][arow] = pa.x; As[nb][akq*4+1][arow] = pa.y;
                As[nb][akq*4+2][arow] = pa.z; As[nb][akq*4+3][arow] = pa.w;
            }
            #pragma unroll
            for (int u = 0; u < 4; u++) {
                int idx = tid + 256 * u, kr = idx >> 6, nq = idx & 63;
                *reinterpret_cast<float4*>(&Bs[nb][kr][nq*4]) = pbv[u];
            }
            __syncthreads();
            buf = nb;
        }
    }

    // col-dependent params (hoisted)
    float biasv[8], gv[8], bbv[8];
    #pragma unroll
    for (int j = 0; j < 8; j++) {
        int c = (j < 4) ? tx*4 + j : 128 + tx*4 + (j - 4);
        biasv[j] = bias[c]; gv[j] = g[c]; bbv[j] = b[c];
    }

    // epilogue: residual + LN per row (warp-wide)
    #pragma unroll
    for (int i = 0; i < 4; i++) {
        int r = bm + ty * 4 + i;
        size_t off = (size_t)r * EQ;
        float4 ra = *reinterpret_cast<const float4*>(&g_x[off + tx*4]);
        float4 rb = *reinterpret_cast<const float4*>(&g_x[off + 128 + tx*4]);
        float res[8] = {ra.x,ra.y,ra.z,ra.w,rb.x,rb.y,rb.z,rb.w};
        float v[8]; float s = 0.0f;
        #pragma unroll
        for (int j = 0; j < 8; j++) { v[j] = acc[i][j] + biasv[j] + res[j]; s += v[j]; }
        float mu = warp_sum(s) * (1.0f / EQ);
        float q = 0.0f;
        #pragma unroll
        for (int j = 0; j < 8; j++) { float d = v[j] - mu; q += d * d; }
        float inv = rsqrtf(warp_sum(q) * (1.0f / EQ) + 1e-12f);
        float4 oa, ob;
        float* op = reinterpret_cast<float*>(&oa);
        float* oq = reinterpret_cast<float*>(&ob);
        #pragma unroll
        for (int j = 0; j < 4; j++) op[j] = (v[j] - mu) * inv * gv[j] + bbv[j];
        #pragma unroll
        for (int j = 4; j < 8; j++) oq[j-4] = (v[j] - mu) * inv * gv[j] + bbv[j];
        *reinterpret_cast<float4*>(&g_x[off + tx*4]) = oa;
        *reinterpret_cast<float4*>(&g_x[off + 128 + tx*4]) = ob;
    }
}

// -------------------- relational attention, 2 batches / 512 threads ----------
__global__ void __launch_bounds__(512)
attn2_kernel(const float* __restrict__ mask)
{
    __shared__ __align__(16) float sk[2][SQ][EQ];   // 14.3 KB
    __shared__ __align__(16) float sek[SQ*SQ][DHQ]; // 12.25 KB
    __shared__ __align__(16) float sev[SQ*SQ][DHQ]; // 12.25 KB
    __shared__ float sc[2][HQ][SQ][8];
    __shared__ float smk[2][SQ];

    int b0 = blockIdx.x * 2, t = threadIdx.x;
    size_t base = (size_t)b0 * SQ * EQ;

    {   // stage k (both batches) + edge tables
        const float4* src = reinterpret_cast<const float4*>(g_k + base);
        float4* dst = reinterpret_cast<float4*>(&sk[0][0][0]);
        for (int i = t; i < 2*SQ*EQ/4; i += 512) dst[i] = src[i];
        const float4* es = reinterpret_cast<const float4*>(g_ek);
        float4* ed = reinterpret_cast<float4*>(&sek[0][0]);
        for (int i = t; i < SQ*SQ*DHQ/4; i += 512) ed[i] = es[i];
        const float4* vs = reinterpret_cast<const float4*>(g_ev);
        float4* vd = reinterpret_cast<float4*>(&sev[0][0]);
        for (int i = t; i < SQ*SQ*DHQ/4; i += 512) vd[i] = vs[i];
        if (t < 2*SQ) (&smk[0][0])[t] = mask[b0*SQ + t];
    }
    __syncthreads();

    if (t < 2*HQ*SQ*SQ) {      // 392 score threads
        int sb = t / 196, r = t % 196, h = r / 49, rr = r % 49, i = rr / 7, j = rr % 7;
        const float* qp = g_q + base + ((size_t)sb*SQ + i) * EQ + h * DHQ;
        const float* kp = &sk[sb][j][h * DHQ];
        const float* ep = &sek[i*SQ + j][0];
        float s = 0.0f;
        #pragma unroll
        for (int d = 0; d < DHQ; d++) s += qp[d] * (kp[d] + ep[d]);
        sc[sb][h][i][j] = s * 0.125f + 1e6f * (smk[sb][i] * smk[sb][j] - 1.0f);
    }
    __syncthreads();

    if (t < 2*HQ*SQ) {         // 56 softmax threads
        int sb = t / 28, r = t % 28, h = r / 7, i = r % 7;
        float mx = sc[sb][h][i][0];
        #pragma unroll
        for (int j = 1; j < 7; j++) mx = fmaxf(mx, sc[sb][h][i][j]);
        float e[7], sum = 0.0f;
        #pragma unroll
        for (int j = 0; j < 7; j++) { e[j] = expf(sc[sb][h][i][j] - mx); sum += e[j]; }
        float inv = 1.0f / sum;
        #pragma unroll
        for (int j = 0; j < 7; j++) sc[sb][h][i][j] = e[j] * inv;
    }
    __syncthreads();

    {   // ctx: 512 threads = 2 batches x 256 cols
        int sb = t >> 8, tt = t & 255, h = tt >> 6, d = tt & 63;
        size_t vb = base + (size_t)sb * SQ * EQ;
        float vreg[SQ];
        #pragma unroll
        for (int j = 0; j < SQ; j++) vreg[j] = g_v[vb + (size_t)j * EQ + tt];
        #pragma unroll
        for (int i = 0; i < SQ; i++) {
            float a = 0.0f;
            #pragma unroll
            for (int j = 0; j < SQ; j++)
                a += sc[sb][h][i][j] * (vreg[j] + sev[i*SQ + j][d]);
            g_ctx[vb + (size_t)i * EQ + tt] = a;
        }
    }
}

// -------------------- single-pass loss ---------------------------------------
// Candidate fc values are O(10); masked entries ~ -1e6 underflow in expf
// exactly as in the reference's shifted computation. Fixed shift 0 is safe.
__global__ void __launch_bounds__(256)
row_loss_kernel(const float* outp, int use_out,
                const float* __restrict__ mtype, const int* __restrict__ label)
{
    __shared__ float sh[8];
    int b = blockIdx.x, t = threadIdx.x;
    const float* row = (use_out ? outp : (const float*)g_fc) + (size_t)b * VOCQ;

    float mt = mtype[b];
    float se = 0.0f, cs = 0.0f;
    for (int vv = t; vv < VOCQ; vv += 256) {
        float f = row[vv];
        se += expf(f);
        cs += ti_of(vv, mt) * f;
    }
    se = blk_sum256(se, sh);
    cs = blk_sum256(cs, sh);

    if (t == 0) {
        float Z = logf(se);
        float C = (mt < 0.0f) ? 200.0f : (float)(VOCQ - 202);
        int lab = label[b];
        float Nc = C - ti_of(lab, mt);
        float lpl = row[lab] - Z;
        float Sti = cs - C * Z;
        g_losses[b] = -(0.9f * lpl + 0.1f * (Sti - lpl) / Nc);
    }
}

__global__ void __launch_bounds__(256)
loss_reduce_kernel(float* __restrict__ out)
{
    __shared__ float sh[8];
    float s = 0.0f;
    for (int i = threadIdx.x; i < BQ; i += 256) s += g_losses[i];
    s = blk_sum256(s, sh);
    if (threadIdx.x == 0) out[0] = s / (float)BQ;
}

// -------------------- launch -------------------------------------------------
extern "C" void kernel_launch(void* const* d_in, const int* in_sizes, int n_in,
                              void* d_out, int out_size)
{
    (void)in_sizes; (void)n_in;
    const int*   input_ids   = (const int*)  d_in[0];
    const float* input_mask  = (const float*)d_in[1];
    const int*   edge_labels = (const int*)  d_in[2];
    const int*   mask_pos    = (const int*)  d_in[3];
    const int*   mask_label  = (const int*)  d_in[4];
    const float* mask_type   = (const float*)d_in[5];
    const float* node_emb    = (const float*)d_in[6];
    const float* ln1_g = (const float*)d_in[7];
    const float* ln1_b = (const float*)d_in[8];
    const float* ek_w  = (const float*)d_in[9];
    const float* ev_w  = (const float*)d_in[10];
    const float* Wq = (const float*)d_in[11]; const float* bq = (const float*)d_in[12];
    const float* Wk = (const float*)d_in[13]; const float* bk = (const float*)d_in[14];
    const float* Wv = (const float*)d_in[15]; const float* bv = (const float*)d_in[16];
    const float* Wo = (const float*)d_in[17]; const float* bo = (const float*)d_in[18];
    const float* lna_g = (const float*)d_in[19]; const float* lna_b = (const float*)d_in[20];
    const float* W1 = (const float*)d_in[21]; const float* b1 = (const float*)d_in[22];
    const float* W2 = (const float*)d_in[23]; const float* b2 = (const float*)d_in[24];
    const float* lnf_g = (const float*)d_in[25]; const float* lnf_b = (const float*)d_in[26];
    const float* ln2_g = (const float*)d_in[27]; const float* ln2_b = (const float*)d_in[28];
    const float* fc2_b = (const float*)d_in[29];

    float* out = (float*)d_out;
    const long long FCN = (long long)BQ * VOCQ;
    float* fc_ptr = nullptr;
    float* loss_ptr = nullptr;
    int fc_in_out = 0;
    if ((long long)out_size >= FCN + 1) {
        loss_ptr = out;
        fc_ptr = out + (long long)out_size - FCN;
        fc_in_out = 1;
    } else if ((long long)out_size == FCN) {
        fc_ptr = out;
        fc_in_out = 1;
    } else {
        loss_ptr = out;
    }

    edge_kernel<<<(SQ * SQ * DHQ + 255) / 256, 256>>>(edge_labels, ek_w, ev_w);
    ln_embed_kernel<<<MROWS, 256>>>(node_emb, input_ids, ln1_g, ln1_b);

    dim3 gqkv(EQ / 64, MROWS / 128, 3);      // (4, 56, 3)
    dim3 gffn1(INNERQ / 64, MROWS / 128);    // (8, 56)

    for (int l = 0; l < LQ; l++) {
        size_t we = (size_t)l * EQ * EQ;
        k_qkv<<<gqkv, 256>>>(Wq + we, Wk + we, Wv + we,
                             bq + l * EQ, bk + l * EQ, bv + l * EQ);
        attn2_kernel<<<BQ / 2, 512>>>(input_mask);
        k_projln<<<MROWS / 32, 256>>>(0, Wo + we, bo + l * EQ,
                                      lna_g + l * EQ, lna_b + l * EQ);
        k_ffn1<<<gffn1, 256>>>(W1 + (size_t)l * EQ * INNERQ, b1 + l * INNERQ);
        k_projln<<<MROWS / 32, 256>>>(1, W2 + (size_t)l * INNERQ * EQ,
                                      b2 + l * EQ,
                                      lnf_g + l * EQ, lnf_b + l * EQ);
    }

    ln_head_kernel<<<BQ, 256>>>(mask_pos, ln2_g, ln2_b);

    dim3 gfc((VOCQ + 63) / 64, BQ / 128);    // (782, 8)
    k_fc<<<gfc, 256>>>(node_emb, fc2_b, mask_type, fc_ptr, fc_in_out);

    row_loss_kernel<<<BQ, 256>>>(fc_ptr, fc_in_out, mask_type, mask_label);
    if (loss_ptr) loss_reduce_kernel<<<1, 256>>>(loss_ptr);
}

// round 7
// speedup vs baseline: 2.1437x; 1.7505x over previous
#include <cuda_runtime.h>
#include <math.h>
#include <stdint.h>

// ---------------------------------------------------------------------------
// GRAN model forward, round 7: all GEMMs on tensor cores (tf32 mma.sync
// m16n8k8), standalone residual-LN kernels, float4-vectorized attention.
// B=1024 S=7 E=256 H=4 DH=64 L=12 INNER=512 VOC=50000
// ---------------------------------------------------------------------------

#define BQ     1024
#define SQ     7
#define EQ     256
#define HQ     4
#define DHQ    64
#define LQ     12
#define INNERQ 512
#define VOCQ   50000
#define MROWS  (BQ*SQ)   // 7168

// -------------------- static device scratch ---------------------------------
__device__ float g_x  [MROWS*EQ];
__device__ float g_q  [MROWS*EQ];
__device__ float g_k  [MROWS*EQ];
__device__ float g_v  [MROWS*EQ];
__device__ float g_ctx[MROWS*EQ];
__device__ float g_o  [MROWS*EQ];
__device__ float g_h  [MROWS*INNERQ];
__device__ float g_ek [SQ*SQ*DHQ];
__device__ float g_ev [SQ*SQ*DHQ];
__device__ float g_hm [BQ*EQ];
__device__ float g_losses[BQ];
__device__ float g_fc [(size_t)BQ*VOCQ];   // fallback fc buffer

// -------------------- helpers -----------------------------------------------
__device__ __forceinline__ float gelu_f(float x) {
    return 0.5f * x * (1.0f + erff(x * 0.70710678118654752440f));
}

__device__ __forceinline__ float warp_sum(float v) {
    #pragma unroll
    for (int o = 16; o > 0; o >>= 1) v += __shfl_xor_sync(0xffffffffu, v, o);
    return v;
}

__device__ __forceinline__ float blk_sum256(float v, float* sh) {
    v = warp_sum(v);
    if ((threadIdx.x & 31) == 0) sh[threadIdx.x >> 5] = v;
    __syncthreads();
    float s = sh[0] + sh[1] + sh[2] + sh[3] + sh[4] + sh[5] + sh[6] + sh[7];
    __syncthreads();
    return s;
}

__device__ __forceinline__ float ti_of(int c, float mt) {
    return (c < 2) ? 0.0f
         : ((c < 202) ? (mt < 0.0f ? 1.0f : 0.0f)
                      : (mt > 0.0f ? 1.0f : 0.0f));
}

__device__ __forceinline__ uint32_t f2tf(float f) {
    uint32_t u; asm("cvt.rna.tf32.f32 %0, %1;" : "=r"(u) : "f"(f)); return u;
}

__device__ __forceinline__ void mma_tf32(float* c, const uint32_t* a, const uint32_t* b) {
    asm volatile(
        "mma.sync.aligned.m16n8k8.row.col.f32.tf32.tf32.f32 "
        "{%0,%1,%2,%3}, {%4,%5,%6,%7}, {%8,%9}, {%0,%1,%2,%3};\n"
        : "+f"(c[0]), "+f"(c[1]), "+f"(c[2]), "+f"(c[3])
        : "r"(a[0]), "r"(a[1]), "r"(a[2]), "r"(a[3]), "r"(b[0]), "r"(b[1]));
}

// -------------------- edge bias precompute -----------------------------------
__global__ void edge_kernel(const int* __restrict__ el,
                            const float* __restrict__ ekw,
                            const float* __restrict__ evw)
{
    int i = blockIdx.x * blockDim.x + threadIdx.x;
    if (i >= SQ * SQ * DHQ) return;
    int ij = i / DHQ, d = i % DHQ;
    int lab = el[ij];
    float s = (lab > 0) ? 1.0f : 0.0f;
    g_ek[i] = ekw[lab * DHQ + d] * s;
    g_ev[i] = evw[lab * DHQ + d] * s;
}

// -------------------- LayerNorms ---------------------------------------------
__global__ void __launch_bounds__(256)
ln_embed_kernel(const float* __restrict__ emb, const int* __restrict__ ids,
                const float* __restrict__ g, const float* __restrict__ b)
{
    __shared__ float sh[8];
    int row = blockIdx.x, t = threadIdx.x;
    float v = emb[(size_t)ids[row] * EQ + t];
    float mu = blk_sum256(v, sh) * (1.0f / EQ);
    float d = v - mu;
    float var = blk_sum256(d * d, sh) * (1.0f / EQ);
    g_x[(size_t)row * EQ + t] = d * rsqrtf(var + 1e-12f) * g[t] + b[t];
}

// g_x = LN(g_x + g_o)
__global__ void __launch_bounds__(256)
ln_res_kernel(const float* __restrict__ g, const float* __restrict__ b)
{
    __shared__ float sh[8];
    int row = blockIdx.x, t = threadIdx.x;
    size_t o = (size_t)row * EQ + t;
    float v = g_x[o] + g_o[o];
    float mu = blk_sum256(v, sh) * (1.0f / EQ);
    float d = v - mu;
    float var = blk_sum256(d * d, sh) * (1.0f / EQ);
    g_x[o] = d * rsqrtf(var + 1e-12f) * g[t] + b[t];
}

__global__ void __launch_bounds__(256)
ln_head_kernel(const int* __restrict__ pos,
               const float* __restrict__ g, const float* __restrict__ b)
{
    __shared__ float sh[8];
    int row = blockIdx.x, t = threadIdx.x;
    float v = gelu_f(g_x[((size_t)row * SQ + pos[row]) * EQ + t]);
    float mu = blk_sum256(v, sh) * (1.0f / EQ);
    float d = v - mu;
    float var = blk_sum256(d * d, sh) * (1.0f / EQ);
    g_hm[(size_t)row * EQ + t] = d * rsqrtf(var + 1e-7f) * g[t] + b[t];
}

// -------------------- tf32 tensor-core GEMM ----------------------------------
// Block 128x128, 256 threads (8 warps 4x2), warp tile 32x64, BK=16, 2-stage.
// C[M,N] = A[M,K] @ B + bias.  BT=false: B[K,N] row-major.  BT=true: B[N,K].
// EPI: 0 bias, 1 bias+gelu, 2 fc (bias + 1e6*(ti-1), scalar stores).
template<bool BT, int EPI>
__device__ __forceinline__
void gemm_tc(const float* __restrict__ A, const float* __restrict__ Bw,
             const float* __restrict__ bias, float* __restrict__ C,
             int N, int K, const float* __restrict__ mtype)
{
    __shared__ uint32_t As[2][128 * 24];   // row-major, row stride 24 (k 0..15)
    __shared__ uint32_t Bs[2][16 * 132];   // k-major, row stride 132 (n 0..127)

    const int tid = threadIdx.x;
    const int w = tid >> 5, lane = tid & 31;
    const int g = lane >> 2, t = lane & 3;
    const int wm = (w & 3) * 32, wn = (w >> 2) * 64;
    const int bm = blockIdx.y * 128, bn = blockIdx.x * 128;

    const int am = tid >> 2, aq = tid & 3;   // A: rows am, am+64; k-quad aq
    const int bk = tid >> 4, bq = tid & 15;  // !BT: k row bk, n-quads bq, bq+16
    const int tn = tid >> 2, tq = tid & 3;   // BT: n rows tn, tn+64; k-quad tq

    float acc[2][8][4] = {};
    float4 pa0, pa1, pb0, pb1;

    // prefetch stage k0 into registers
    auto loadg = [&](int k0) {
        pa0 = *(const float4*)(A + (size_t)(bm + am) * K + k0 + aq * 4);
        pa1 = *(const float4*)(A + (size_t)(bm + am + 64) * K + k0 + aq * 4);
        if (!BT) {
            pb0 = *(const float4*)(Bw + (size_t)(k0 + bk) * N + bn + bq * 4);
            pb1 = *(const float4*)(Bw + (size_t)(k0 + bk) * N + bn + 64 + bq * 4);
        } else {
            int n0 = bn + tn, n1 = bn + tn + 64;
            pb0 = (n0 < N) ? *(const float4*)(Bw + (size_t)n0 * K + k0 + tq * 4)
                           : make_float4(0.f, 0.f, 0.f, 0.f);
            pb1 = (n1 < N) ? *(const float4*)(Bw + (size_t)n1 * K + k0 + tq * 4)
                           : make_float4(0.f, 0.f, 0.f, 0.f);
        }
    };

    auto storesm = [&](int buf) {
        uint4 ua0 = make_uint4(f2tf(pa0.x), f2tf(pa0.y), f2tf(pa0.z), f2tf(pa0.w));
        uint4 ua1 = make_uint4(f2tf(pa1.x), f2tf(pa1.y), f2tf(pa1.z), f2tf(pa1.w));
        *(uint4*)&As[buf][am * 24 + aq * 4] = ua0;
        *(uint4*)&As[buf][(am + 64) * 24 + aq * 4] = ua1;
        if (!BT) {
            uint4 ub0 = make_uint4(f2tf(pb0.x), f2tf(pb0.y), f2tf(pb0.z), f2tf(pb0.w));
            uint4 ub1 = make_uint4(f2tf(pb1.x), f2tf(pb1.y), f2tf(pb1.z), f2tf(pb1.w));
            *(uint4*)&Bs[buf][bk * 132 + bq * 4] = ub0;
            *(uint4*)&Bs[buf][bk * 132 + 64 + bq * 4] = ub1;
        } else {
            uint32_t u0[4] = {f2tf(pb0.x), f2tf(pb0.y), f2tf(pb0.z), f2tf(pb0.w)};
            uint32_t u1[4] = {f2tf(pb1.x), f2tf(pb1.y), f2tf(pb1.z), f2tf(pb1.w)};
            #pragma unroll
            for (int i = 0; i < 4; i++) {
                int ii = (i + tq) & 3;   // conflict-avoiding store order
                Bs[buf][(tq * 4 + ii) * 132 + tn] = u0[ii];
                Bs[buf][(tq * 4 + ii) * 132 + tn + 64] = u1[ii];
            }
        }
    };

    auto compute = [&](int buf) {
        #pragma unroll
        for (int ks = 0; ks < 2; ks++) {
            const int ko = ks * 8;
            uint32_t bfr[8][2];
            #pragma unroll
            for (int ni = 0; ni < 8; ni++) {
                int n = wn + ni * 8 + g;
                bfr[ni][0] = Bs[buf][(ko + 2 * t) * 132 + n];
                bfr[ni][1] = Bs[buf][(ko + 2 * t + 1) * 132 + n];
            }
            uint32_t afr[2][4];
            #pragma unroll
            for (int mi = 0; mi < 2; mi++) {
                int m0 = wm + mi * 16 + g;
                uint2 p0 = *(const uint2*)&As[buf][m0 * 24 + ko + 2 * t];
                uint2 p1 = *(const uint2*)&As[buf][(m0 + 8) * 24 + ko + 2 * t];
                afr[mi][0] = p0.x; afr[mi][1] = p0.y;
                afr[mi][2] = p1.x; afr[mi][3] = p1.y;
            }
            #pragma unroll
            for (int mi = 0; mi < 2; mi++)
                #pragma unroll
                for (int ni = 0; ni < 8; ni++)
                    mma_tf32(&acc[mi][ni][0], afr[mi], bfr[ni]);
        }
    };

    loadg(0); storesm(0); __syncthreads();
    const int nk = K >> 4;
    int buf = 0;
    for (int s = 0; s < nk; s++) {
        const bool more = (s + 1 < nk);
        if (more) loadg((s + 1) << 4);
        compute(buf);
        if (more) { storesm(buf ^ 1); __syncthreads(); buf ^= 1; }
    }

    // ---- epilogue ----
    #pragma unroll
    for (int mi = 0; mi < 2; mi++) {
        int r0 = bm + wm + mi * 16 + g;
        int r8 = r0 + 8;
        float mt0 = 0.f, mt8 = 0.f;
        if (EPI == 2) { mt0 = mtype[r0]; mt8 = mtype[r8]; }
        #pragma unroll
        for (int ni = 0; ni < 8; ni++) {
            int c0 = bn + wn + ni * 8 + 2 * t;
            const float* a4 = acc[mi][ni];
            if (EPI == 2) {
                #pragma unroll
                for (int jj = 0; jj < 2; jj++) {
                    int c = c0 + jj;
                    if (c < N) {
                        float bv = bias[c];
                        C[(size_t)r0 * N + c] = a4[jj] + bv + 1e6f * (ti_of(c, mt0) - 1.0f);
                        C[(size_t)r8 * N + c] = a4[2 + jj] + bv + 1e6f * (ti_of(c, mt8) - 1.0f);
                    }
                }
            } else {
                float b0v = bias[c0], b1v = bias[c0 + 1];
                float v0 = a4[0] + b0v, v1 = a4[1] + b1v;
                float v2 = a4[2] + b0v, v3 = a4[3] + b1v;
                if (EPI == 1) { v0 = gelu_f(v0); v1 = gelu_f(v1); v2 = gelu_f(v2); v3 = gelu_f(v3); }
                *(float2*)(C + (size_t)r0 * N + c0) = make_float2(v0, v1);
                *(float2*)(C + (size_t)r8 * N + c0) = make_float2(v2, v3);
            }
        }
    }
}

// ---- wrappers (device globals wired inside kernels) -------------------------
__global__ void __launch_bounds__(256)
k_qkv_tc(const float* __restrict__ Wq, const float* __restrict__ Wk,
         const float* __restrict__ Wv, const float* __restrict__ bq,
         const float* __restrict__ bk, const float* __restrict__ bv)
{
    int z = blockIdx.z;
    const float* W = (z == 0) ? Wq : (z == 1) ? Wk : Wv;
    const float* b = (z == 0) ? bq : (z == 1) ? bk : bv;
    float* C = (z == 0) ? g_q : (z == 1) ? g_k : g_v;
    gemm_tc<false, 0>(g_x, W, b, C, EQ, EQ, nullptr);
}

__global__ void __launch_bounds__(256)
k_oproj_tc(const float* __restrict__ W, const float* __restrict__ b)
{ gemm_tc<false, 0>(g_ctx, W, b, g_o, EQ, EQ, nullptr); }

__global__ void __launch_bounds__(256)
k_ffn1_tc(const float* __restrict__ W, const float* __restrict__ b)
{ gemm_tc<false, 1>(g_x, W, b, g_h, INNERQ, EQ, nullptr); }

__global__ void __launch_bounds__(256)
k_ffn2_tc(const float* __restrict__ W, const float* __restrict__ b)
{ gemm_tc<false, 0>(g_h, W, b, g_o, EQ, INNERQ, nullptr); }

__global__ void __launch_bounds__(256)
k_fc_tc(const float* __restrict__ emb, const float* __restrict__ bias,
        const float* __restrict__ mtype, float* outp, int use_out)
{
    float* C = use_out ? outp : g_fc;
    gemm_tc<true, 2>(g_hm, emb, bias, C, VOCQ, EQ, mtype);
}

// -------------------- relational attention, float4 dots ----------------------
__global__ void __launch_bounds__(512)
attn3_kernel(const float* __restrict__ mask)
{
    __shared__ __align__(16) float4 sk4[2][SQ][EQ/4];   // 14.3 KB
    __shared__ __align__(16) float4 sek4[SQ*SQ][DHQ/4]; // 12.25 KB
    __shared__ __align__(16) float  sev[SQ*SQ][DHQ];    // 12.25 KB
    __shared__ float sc[2][HQ][SQ][8];
    __shared__ float smk[2][SQ];

    int b0 = blockIdx.x * 2, t = threadIdx.x;
    size_t base = (size_t)b0 * SQ * EQ;

    {   // stage k (both batches) + edge tables
        const float4* src = (const float4*)(g_k + base);
        float4* dst = &sk4[0][0][0];
        for (int i = t; i < 2*SQ*EQ/4; i += 512) dst[i] = src[i];
        const float4* es = (const float4*)g_ek;
        float4* ed = &sek4[0][0];
        for (int i = t; i < SQ*SQ*DHQ/4; i += 512) ed[i] = es[i];
        const float4* vs = (const float4*)g_ev;
        float4* vd = (float4*)&sev[0][0];
        for (int i = t; i < SQ*SQ*DHQ/4; i += 512) vd[i] = vs[i];
        if (t < 2*SQ) (&smk[0][0])[t] = mask[b0*SQ + t];
    }
    __syncthreads();

    if (t < 2*HQ*SQ*SQ) {      // 392 score threads, float4 dot with 4 accs
        int sb = t / 196, r = t % 196, h = r / 49, rr = r % 49, i = rr / 7, j = rr % 7;
        const float4* qp = (const float4*)(g_q + base + ((size_t)sb*SQ + i) * EQ + h * DHQ);
        const float4* kp = &sk4[sb][j][h * 16];
        const float4* ep = &sek4[i*SQ + j][0];
        float s0 = 0.f, s1 = 0.f, s2 = 0.f, s3 = 0.f;
        #pragma unroll
        for (int d = 0; d < 16; d += 4) {
            float4 q0 = qp[d],   k0 = kp[d],   e0 = ep[d];
            float4 q1 = qp[d+1], k1 = kp[d+1], e1 = ep[d+1];
            float4 q2 = qp[d+2], k2 = kp[d+2], e2 = ep[d+2];
            float4 q3 = qp[d+3], k3 = kp[d+3], e3 = ep[d+3];
            s0 += q0.x*(k0.x+e0.x) + q0.y*(k0.y+e0.y) + q0.z*(k0.z+e0.z) + q0.w*(k0.w+e0.w);
            s1 += q1.x*(k1.x+e1.x) + q1.y*(k1.y+e1.y) + q1.z*(k1.z+e1.z) + q1.w*(k1.w+e1.w);
            s2 += q2.x*(k2.x+e2.x) + q2.y*(k2.y+e2.y) + q2.z*(k2.z+e2.z) + q2.w*(k2.w+e2.w);
            s3 += q3.x*(k3.x+e3.x) + q3.y*(k3.y+e3.y) + q3.z*(k3.z+e3.z) + q3.w*(k3.w+e3.w);
        }
        float s = (s0 + s1) + (s2 + s3);
        sc[sb][h][i][j] = s * 0.125f + 1e6f * (smk[sb][i] * smk[sb][j] - 1.0f);
    }
    __syncthreads();

    if (t < 2*HQ*SQ) {         // 56 softmax threads
        int sb = t / 28, r = t % 28, h = r / 7, i = r % 7;
        float mx = sc[sb][h][i][0];
        #pragma unroll
        for (int j = 1; j < 7; j++) mx = fmaxf(mx, sc[sb][h][i][j]);
        float e[7], sum = 0.0f;
        #pragma unroll
        for (int j = 0; j < 7; j++) { e[j] = expf(sc[sb][h][i][j] - mx); sum += e[j]; }
        float inv = 1.0f / sum;
        #pragma unroll
        for (int j = 0; j < 7; j++) sc[sb][h][i][j] = e[j] * inv;
    }
    __syncthreads();

    {   // ctx: 512 threads = 2 batches x 256 cols
        int sb = t >> 8, tt = t & 255, h = tt >> 6, d = tt & 63;
        size_t vb = base + (size_t)sb * SQ * EQ;
        float vreg[SQ];
        #pragma unroll
        for (int j = 0; j < SQ; j++) vreg[j] = g_v[vb + (size_t)j * EQ + tt];
        #pragma unroll
        for (int i = 0; i < SQ; i++) {
            float a = 0.0f;
            #pragma unroll
            for (int j = 0; j < SQ; j++)
                a += sc[sb][h][i][j] * (vreg[j] + sev[i*SQ + j][d]);
            g_ctx[vb + (size_t)i * EQ + tt] = a;
        }
    }
}

// -------------------- single-pass loss ---------------------------------------
__global__ void __launch_bounds__(256)
row_loss_kernel(const float* outp, int use_out,
                const float* __restrict__ mtype, const int* __restrict__ label)
{
    __shared__ float sh[8];
    int b = blockIdx.x, t = threadIdx.x;
    const float* row = (use_out ? outp : (const float*)g_fc) + (size_t)b * VOCQ;

    float mt = mtype[b];
    float se = 0.0f, cs = 0.0f;
    for (int vv = t; vv < VOCQ; vv += 256) {
        float f = row[vv];
        se += expf(f);
        cs += ti_of(vv, mt) * f;
    }
    se = blk_sum256(se, sh);
    cs = blk_sum256(cs, sh);

    if (t == 0) {
        float Z = logf(se);
        float C = (mt < 0.0f) ? 200.0f : (float)(VOCQ - 202);
        int lab = label[b];
        float Nc = C - ti_of(lab, mt);
        float lpl = row[lab] - Z;
        float Sti = cs - C * Z;
        g_losses[b] = -(0.9f * lpl + 0.1f * (Sti - lpl) / Nc);
    }
}

__global__ void __launch_bounds__(256)
loss_reduce_kernel(float* __restrict__ out)
{
    __shared__ float sh[8];
    float s = 0.0f;
    for (int i = threadIdx.x; i < BQ; i += 256) s += g_losses[i];
    s = blk_sum256(s, sh);
    if (threadIdx.x == 0) out[0] = s / (float)BQ;
}

// -------------------- launch -------------------------------------------------
extern "C" void kernel_launch(void* const* d_in, const int* in_sizes, int n_in,
                              void* d_out, int out_size)
{
    (void)in_sizes; (void)n_in;
    const int*   input_ids   = (const int*)  d_in[0];
    const float* input_mask  = (const float*)d_in[1];
    const int*   edge_labels = (const int*)  d_in[2];
    const int*   mask_pos    = (const int*)  d_in[3];
    const int*   mask_label  = (const int*)  d_in[4];
    const float* mask_type   = (const float*)d_in[5];
    const float* node_emb    = (const float*)d_in[6];
    const float* ln1_g = (const float*)d_in[7];
    const float* ln1_b = (const float*)d_in[8];
    const float* ek_w  = (const float*)d_in[9];
    const float* ev_w  = (const float*)d_in[10];
    const float* Wq = (const float*)d_in[11]; const float* bq = (const float*)d_in[12];
    const float* Wk = (const float*)d_in[13]; const float* bk = (const float*)d_in[14];
    const float* Wv = (const float*)d_in[15]; const float* bv = (const float*)d_in[16];
    const float* Wo = (const float*)d_in[17]; const float* bo = (const float*)d_in[18];
    const float* lna_g = (const float*)d_in[19]; const float* lna_b = (const float*)d_in[20];
    const float* W1 = (const float*)d_in[21]; const float* b1 = (const float*)d_in[22];
    const float* W2 = (const float*)d_in[23]; const float* b2 = (const float*)d_in[24];
    const float* lnf_g = (const float*)d_in[25]; const float* lnf_b = (const float*)d_in[26];
    const float* ln2_g = (const float*)d_in[27]; const float* ln2_b = (const float*)d_in[28];
    const float* fc2_b = (const float*)d_in[29];

    float* out = (float*)d_out;
    const long long FCN = (long long)BQ * VOCQ;
    float* fc_ptr = nullptr;
    float* loss_ptr = nullptr;
    int fc_in_out = 0;
    if ((long long)out_size >= FCN + 1) {      // [loss, fc_out]
        loss_ptr = out;
        fc_ptr = out + (long long)out_size - FCN;
        fc_in_out = 1;
    } else if ((long long)out_size == FCN) {   // fc only
        fc_ptr = out;
        fc_in_out = 1;
    } else {                                   // loss only
        loss_ptr = out;
    }

    edge_kernel<<<(SQ * SQ * DHQ + 255) / 256, 256>>>(edge_labels, ek_w, ev_w);
    ln_embed_kernel<<<MROWS, 256>>>(node_emb, input_ids, ln1_g, ln1_b);

    dim3 gqkv(EQ / 128, MROWS / 128, 3);      // (2, 56, 3)
    dim3 gff1(INNERQ / 128, MROWS / 128);     // (4, 56)
    dim3 g256(EQ / 128, MROWS / 128);         // (2, 56)

    for (int l = 0; l < LQ; l++) {
        size_t we = (size_t)l * EQ * EQ;
        k_qkv_tc<<<gqkv, 256>>>(Wq + we, Wk + we, Wv + we,
                                bq + l * EQ, bk + l * EQ, bv + l * EQ);
        attn3_kernel<<<BQ / 2, 512>>>(input_mask);
        k_oproj_tc<<<g256, 256>>>(Wo + we, bo + l * EQ);
        ln_res_kernel<<<MROWS, 256>>>(lna_g + l * EQ, lna_b + l * EQ);
        k_ffn1_tc<<<gff1, 256>>>(W1 + (size_t)l * EQ * INNERQ, b1 + l * INNERQ);
        k_ffn2_tc<<<g256, 256>>>(W2 + (size_t)l * INNERQ * EQ, b2 + l * EQ);
        ln_res_kernel<<<MROWS, 256>>>(lnf_g + l * EQ, lnf_b + l * EQ);
    }

    ln_head_kernel<<<BQ, 256>>>(mask_pos, ln2_g, ln2_b);

    dim3 gfc((VOCQ + 127) / 128, BQ / 128);   // (391, 8)
    k_fc_tc<<<gfc, 256>>>(node_emb, fc2_b, mask_type, fc_ptr, fc_in_out);

    row_loss_kernel<<<BQ, 256>>>(fc_ptr, fc_in_out, mask_type, mask_label);
    if (loss_ptr) loss_reduce_kernel<<<1, 256>>>(loss_ptr);
}